// round 1
// baseline (speedup 1.0000x reference)
#include <cuda_runtime.h>
#include <cstdint>

#define T_LEN  512
#define BATCH  64
#define EMBED  1024
#define HIDDEN 1024
#define BH     (BATCH * HIDDEN)

// ---------------- f32x2 packed-FMA helpers (sm_100a) ----------------
__device__ __forceinline__ unsigned long long pack2(float x, float y) {
    unsigned long long r;
    asm("mov.b64 %0, {%1, %2};" : "=l"(r) : "f"(x), "f"(y));
    return r;
}
__device__ __forceinline__ void unpack2(unsigned long long v, float& x, float& y) {
    asm("mov.b64 {%0, %1}, %2;" : "=f"(x), "=f"(y) : "l"(v));
}
__device__ __forceinline__ void ffma2(unsigned long long& acc,
                                      unsigned long long a,
                                      unsigned long long b) {
    asm("fma.rn.f32x2 %0, %1, %2, %0;" : "+l"(acc) : "l"(a), "l"(b));
}

// ---------------------------------------------------------------
// Kernel 1: Z = gather(emb1, src) @ W_ih^T + b_ih + b_hh
// Written directly into d_out (outs region). Tile 64x64, BK=16.
// 256 threads, 4x4 microtile, f32x2 FMAs (acc pairs along n).
// ---------------------------------------------------------------
__global__ __launch_bounds__(256) void zgemm_kernel(
    const int*   __restrict__ src,
    const float* __restrict__ emb,
    const float* __restrict__ Wih,
    const float* __restrict__ bih,
    const float* __restrict__ bhh,
    float*       __restrict__ out)
{
    __shared__ float As[16][68];   // [k][m], pitch 68 floats = 272B (16B aligned)
    __shared__ float Bs[16][68];   // [k][n]

    const int bm  = blockIdx.x * 64;          // token-row tile
    const int bn  = blockIdx.y * 64;          // hidden-col tile
    const int tid = threadIdx.x;

    // staging: thread t loads row lr, k-quad lk (one float4 each for A and B)
    const int lr = tid >> 2;                  // 0..63
    const int lk = (tid & 3) * 4;             // 0,4,8,12

    const float* arow = emb + (long)src[bm + lr] * EMBED;
    const float* brow = Wih + (long)(bn + lr) * EMBED;

    // compute mapping: 16x16 thread grid, 4m x 4n microtile
    const int tn = (tid & 15) * 4;
    const int tm = (tid >> 4) * 4;

    unsigned long long acc[4][2];
#pragma unroll
    for (int i = 0; i < 4; i++) { acc[i][0] = 0ull; acc[i][1] = 0ull; }

    for (int k0 = 0; k0 < EMBED; k0 += 16) {
        float4 av = *(const float4*)(arow + k0 + lk);
        float4 bv = *(const float4*)(brow + k0 + lk);
        __syncthreads();
        As[lk + 0][lr] = av.x; As[lk + 1][lr] = av.y;
        As[lk + 2][lr] = av.z; As[lk + 3][lr] = av.w;
        Bs[lk + 0][lr] = bv.x; Bs[lk + 1][lr] = bv.y;
        Bs[lk + 2][lr] = bv.z; Bs[lk + 3][lr] = bv.w;
        __syncthreads();
#pragma unroll
        for (int k = 0; k < 16; k++) {
            float4     a  = *(const float4*)&As[k][tm];
            ulonglong2 b2 = *(const ulonglong2*)&Bs[k][tn];  // (n0,n1),(n2,n3)
            unsigned long long aa;
            aa = pack2(a.x, a.x); ffma2(acc[0][0], b2.x, aa); ffma2(acc[0][1], b2.y, aa);
            aa = pack2(a.y, a.y); ffma2(acc[1][0], b2.x, aa); ffma2(acc[1][1], b2.y, aa);
            aa = pack2(a.z, a.z); ffma2(acc[2][0], b2.x, aa); ffma2(acc[2][1], b2.y, aa);
            aa = pack2(a.w, a.w); ffma2(acc[3][0], b2.x, aa); ffma2(acc[3][1], b2.y, aa);
        }
    }

#pragma unroll
    for (int i = 0; i < 4; i++) {
        const long row = bm + tm + i;
#pragma unroll
        for (int p = 0; p < 2; p++) {
            const int col = bn + tn + p * 2;
            float x, y;
            unpack2(acc[i][p], x, y);
            float2 v;
            v.x = x + bih[col]     + bhh[col];
            v.y = y + bih[col + 1] + bhh[col + 1];
            *(float2*)(out + row * HIDDEN + col) = v;
        }
    }
}

// ---------------------------------------------------------------
// Kernel 2: one RNN step (t >= 1).
//   z (in/out) = d_out + t*BH holds Z_t on entry, h_t on exit.
//   h_t[b,j] = relu(tanh(Z_t[b,j] + sum_k hprev[b,k] * Whh[j,k]))
// Tile: [64 b x 8 j], grid 128, 128 threads, microtile 4b x 1j.
// ---------------------------------------------------------------
__global__ __launch_bounds__(128) void step_kernel(
    const float* __restrict__ Whh,
    const float* __restrict__ hprev,
    float*       __restrict__ z)
{
    __shared__ float Hs[16][68];   // [k][b]
    __shared__ float Ws[16][8];    // [k][j]

    const int tid = threadIdx.x;
    const int j0  = blockIdx.x * 8;
    const int jt  = tid & 7;            // 0..7
    const int bt  = (tid >> 3) * 4;     // 0..60 (16 b-groups)

    // W loader: 8 j x 16 k = 128 floats, 1/thread
    const int wj = tid >> 4;            // 0..7
    const int wk = tid & 15;            // 0..15

    // H loader: 64 rows x 16 k = 1024 floats = 2 float4/thread
    const int hr = tid >> 2;            // 0..31
    const int hq = (tid & 3) * 4;       // 0,4,8,12

    unsigned long long acc0 = 0ull, acc1 = 0ull;

    for (int k0 = 0; k0 < HIDDEN; k0 += 16) {
        float4 ha = *(const float4*)(hprev + (long)hr        * HIDDEN + k0 + hq);
        float4 hb = *(const float4*)(hprev + (long)(32 + hr) * HIDDEN + k0 + hq);
        float  wv = Whh[(long)(j0 + wj) * HIDDEN + k0 + wk];
        __syncthreads();
        Hs[hq + 0][hr] = ha.x; Hs[hq + 1][hr] = ha.y;
        Hs[hq + 2][hr] = ha.z; Hs[hq + 3][hr] = ha.w;
        Hs[hq + 0][32 + hr] = hb.x; Hs[hq + 1][32 + hr] = hb.y;
        Hs[hq + 2][32 + hr] = hb.z; Hs[hq + 3][32 + hr] = hb.w;
        Ws[wk][wj] = wv;
        __syncthreads();
#pragma unroll
        for (int k = 0; k < 16; k++) {
            ulonglong2 h2 = *(const ulonglong2*)&Hs[k][bt];  // (b0,b1),(b2,b3)
            float w = Ws[k][jt];
            unsigned long long ww = pack2(w, w);
            ffma2(acc0, h2.x, ww);
            ffma2(acc1, h2.y, ww);
        }
    }

    float s0, s1, s2, s3;
    unpack2(acc0, s0, s1);
    unpack2(acc1, s2, s3);
    const int col = j0 + jt;
    float* p0 = z + (long)(bt + 0) * HIDDEN + col;
    float* p1 = z + (long)(bt + 1) * HIDDEN + col;
    float* p2 = z + (long)(bt + 2) * HIDDEN + col;
    float* p3 = z + (long)(bt + 3) * HIDDEN + col;
    *p0 = fmaxf(tanhf(*p0 + s0), 0.0f);
    *p1 = fmaxf(tanhf(*p1 + s1), 0.0f);
    *p2 = fmaxf(tanhf(*p2 + s2), 0.0f);
    *p3 = fmaxf(tanhf(*p3 + s3), 0.0f);
}

// t = 0: h0 = relu(tanh(Z_0)) in place (h_{-1} == 0)
__global__ __launch_bounds__(256) void act0_kernel(float* __restrict__ z)
{
    const int i = blockIdx.x * 256 + threadIdx.x;
    const long base = (long)i * 4;
    float4 v = *(float4*)(z + base);
    v.x = fmaxf(tanhf(v.x), 0.0f);
    v.y = fmaxf(tanhf(v.y), 0.0f);
    v.z = fmaxf(tanhf(v.z), 0.0f);
    v.w = fmaxf(tanhf(v.w), 0.0f);
    *(float4*)(z + base) = v;
}

// h_last = outs[T-1]
__global__ __launch_bounds__(256) void copy_kernel(const float* __restrict__ s,
                                                   float* __restrict__ d)
{
    const int i = blockIdx.x * 256 + threadIdx.x;
    const long base = (long)i * 4;
    *(float4*)(d + base) = *(const float4*)(s + base);
}

extern "C" void kernel_launch(void* const* d_in, const int* in_sizes, int n_in,
                              void* d_out, int out_size)
{
    const int*   src = (const int*)  d_in[0];
    const float* emb = (const float*)d_in[1];
    const float* Wih = (const float*)d_in[2];
    const float* Whh = (const float*)d_in[3];
    const float* bih = (const float*)d_in[4];
    const float* bhh = (const float*)d_in[5];
    float* out = (float*)d_out;

    // 1) Z for all timesteps straight into the outs region of d_out
    dim3 g1(T_LEN * BATCH / 64, HIDDEN / 64);   // (512, 16)
    zgemm_kernel<<<g1, 256>>>(src, emb, Wih, bih, bhh, out);

    // 2) t = 0 activation (no recurrent term)
    act0_kernel<<<BH / (256 * 4), 256>>>(out);

    // 3) sequential recurrence, in place
    for (int t = 1; t < T_LEN; t++) {
        step_kernel<<<HIDDEN / 8, 128>>>(Whh,
                                         out + (long)(t - 1) * BH,
                                         out + (long)t * BH);
    }

    // 4) h_last = outs[T-1]
    copy_kernel<<<BH / (256 * 4), 256>>>(out + (long)(T_LEN - 1) * BH,
                                         out + (long)T_LEN * BH);
}

// round 2
// speedup vs baseline: 3.1630x; 3.1630x over previous
#include <cuda_runtime.h>
#include <cstdint>

#define T_LEN  512
#define BATCH  64
#define EMBED  1024
#define HIDDEN 1024
#define BH     (BATCH * HIDDEN)
#define NB     128            // persistent blocks (<= SM count, 1 block/SM)
#define NTHR   256

// ---------------- f32x2 packed-FMA helpers ----------------
__device__ __forceinline__ unsigned long long pack2(float x, float y) {
    unsigned long long r;
    asm("mov.b64 %0, {%1, %2};" : "=l"(r) : "f"(x), "f"(y));
    return r;
}
__device__ __forceinline__ void unpack2(unsigned long long v, float& x, float& y) {
    asm("mov.b64 {%0, %1}, %2;" : "=f"(x), "=f"(y) : "l"(v));
}
__device__ __forceinline__ void ffma2(unsigned long long& acc,
                                      unsigned long long a,
                                      unsigned long long b) {
    asm("fma.rn.f32x2 %0, %1, %2, %0;" : "+l"(acc) : "l"(a), "l"(b));
}

// global spin-barrier counter (reset by reset_bar before each persistent launch)
__device__ unsigned g_bar;

__global__ void reset_bar() { g_bar = 0u; }

// ---------------------------------------------------------------
// Kernel 1: Z = gather(emb1, src) @ W_ih^T + b_ih + b_hh  -> d_out rows
// ---------------------------------------------------------------
__global__ __launch_bounds__(256) void zgemm_kernel(
    const int*   __restrict__ src,
    const float* __restrict__ emb,
    const float* __restrict__ Wih,
    const float* __restrict__ bih,
    const float* __restrict__ bhh,
    float*       __restrict__ out)
{
    __shared__ float As[16][68];
    __shared__ float Bs[16][68];

    const int bm  = blockIdx.x * 64;
    const int bn  = blockIdx.y * 64;
    const int tid = threadIdx.x;

    const int lr = tid >> 2;
    const int lk = (tid & 3) * 4;

    const float* arow = emb + (long)src[bm + lr] * EMBED;
    const float* brow = Wih + (long)(bn + lr) * EMBED;

    const int tn = (tid & 15) * 4;
    const int tm = (tid >> 4) * 4;

    unsigned long long acc[4][2];
#pragma unroll
    for (int i = 0; i < 4; i++) { acc[i][0] = 0ull; acc[i][1] = 0ull; }

    for (int k0 = 0; k0 < EMBED; k0 += 16) {
        float4 av = *(const float4*)(arow + k0 + lk);
        float4 bv = *(const float4*)(brow + k0 + lk);
        __syncthreads();
        As[lk + 0][lr] = av.x; As[lk + 1][lr] = av.y;
        As[lk + 2][lr] = av.z; As[lk + 3][lr] = av.w;
        Bs[lk + 0][lr] = bv.x; Bs[lk + 1][lr] = bv.y;
        Bs[lk + 2][lr] = bv.z; Bs[lk + 3][lr] = bv.w;
        __syncthreads();
#pragma unroll
        for (int k = 0; k < 16; k++) {
            float4     a  = *(const float4*)&As[k][tm];
            ulonglong2 b2 = *(const ulonglong2*)&Bs[k][tn];
            unsigned long long aa;
            aa = pack2(a.x, a.x); ffma2(acc[0][0], b2.x, aa); ffma2(acc[0][1], b2.y, aa);
            aa = pack2(a.y, a.y); ffma2(acc[1][0], b2.x, aa); ffma2(acc[1][1], b2.y, aa);
            aa = pack2(a.z, a.z); ffma2(acc[2][0], b2.x, aa); ffma2(acc[2][1], b2.y, aa);
            aa = pack2(a.w, a.w); ffma2(acc[3][0], b2.x, aa); ffma2(acc[3][1], b2.y, aa);
        }
    }

#pragma unroll
    for (int i = 0; i < 4; i++) {
        const long row = bm + tm + i;
#pragma unroll
        for (int p = 0; p < 2; p++) {
            const int col = bn + tn + p * 2;
            float x, y;
            unpack2(acc[i][p], x, y);
            float2 v;
            v.x = x + bih[col]     + bhh[col];
            v.y = y + bih[col + 1] + bhh[col + 1];
            *(float2*)(out + row * HIDDEN + col) = v;
        }
    }
}

// ---------------------------------------------------------------
// Kernel 2: persistent RNN recurrence.
// 128 blocks, each owns 16b x 32j of the output for all timesteps.
// Whh slice in smem (loaded once). Grid-wide spin barrier per step.
// ---------------------------------------------------------------
__global__ __launch_bounds__(NTHR, 1) void rnn_persist(
    const float* __restrict__ Whh,
    float*       __restrict__ out)
{
    extern __shared__ float sm[];
    float* Wsm = sm;                  // [32][1024] = 128KB
    float* Hsm = sm + 32 * 1024;      // [16][1024] = 64KB, aliased as scratch
    float* Ssm = Hsm;                 // [8 warps][64*33] = 67.6KB

    const int tid  = threadIdx.x;
    const int lane = tid & 31;
    const int w    = tid >> 5;
    const int bt   = blockIdx.x >> 5;    // 0..3
    const int jt   = blockIdx.x & 31;    // 0..31
    const int b0   = bt * 16;
    const int j0   = jt * 32;
    const int wb   = (w >> 2) * 8;       // warp b-offset within tile
    const int wj   = (w & 3) * 8;        // warp j-offset within tile

    // Load Whh slice [j0, j0+32) rows into Wsm once (row-major [j][k])
    for (int i = tid; i < 32 * 256; i += NTHR) {
        int j  = i >> 8;
        int c4 = i & 255;
        float4 v = *((const float4*)(Whh + (size_t)(j0 + j) * HIDDEN) + c4);
        *((float4*)(Wsm + j * 1024) + c4) = v;
    }

    // t = 0: h0 = relu(tanh(Z_0)) on own slice (h_{-1} == 0)
    for (int i = tid; i < 512; i += NTHR) {
        int b = b0 + (i >> 5);
        int j = j0 + (i & 31);
        float z = out[(size_t)b * HIDDEN + j];
        out[(size_t)b * HIDDEN + j] = fmaxf(tanhf(z), 0.0f);
    }
    __syncthreads();

    for (int t = 1; t < T_LEN; t++) {
        // grid barrier: all writes of step t-1 visible
        if (tid == 0) {
            __threadfence();
            atomicAdd(&g_bar, 1u);
            const unsigned tgt = (unsigned)t * NB;
            volatile unsigned* p = &g_bar;
            while (*p < tgt) { }
            __threadfence();
        }
        __syncthreads();

        // stage h_{t-1} rows [b0, b0+16) into smem (L1-bypass: cross-SM data)
        const float4* hp = (const float4*)(out + (size_t)(t - 1) * BH
                                               + (size_t)b0 * HIDDEN);
        for (int i = tid; i < 16 * 256; i += NTHR) {
            ((float4*)Hsm)[i] = __ldcg(hp + i);
        }
        __syncthreads();

        // main loop: lane owns k = 2*lane + 64*i (32 k's), 8b x 8j microtile
        unsigned long long acc[8][8];
#pragma unroll
        for (int b = 0; b < 8; b++)
#pragma unroll
            for (int j = 0; j < 8; j++) acc[b][j] = 0ull;

#pragma unroll 2
        for (int i = 0; i < 16; i++) {
            const int k = 2 * lane + 64 * i;
            unsigned long long hv[8], wv[8];
#pragma unroll
            for (int b = 0; b < 8; b++)
                hv[b] = *(const unsigned long long*)(Hsm + (wb + b) * 1024 + k);
#pragma unroll
            for (int j = 0; j < 8; j++)
                wv[j] = *(const unsigned long long*)(Wsm + (wj + j) * 1024 + k);
#pragma unroll
            for (int b = 0; b < 8; b++)
#pragma unroll
                for (int j = 0; j < 8; j++)
                    ffma2(acc[b][j], hv[b], wv[j]);
        }
        __syncthreads();   // everyone done reading Hsm before scratch reuse

        // cross-lane reduction via padded scratch (warp-private region)
        float* S = Ssm + w * (64 * 33);
#pragma unroll
        for (int b = 0; b < 8; b++)
#pragma unroll
            for (int j = 0; j < 8; j++) {
                float x, y;
                unpack2(acc[b][j], x, y);
                S[(b * 8 + j) * 33 + lane] = x + y;
            }
        __syncwarp();

        float* zrow = out + (size_t)t * BH;
#pragma unroll
        for (int h = 0; h < 2; h++) {
            const int o = lane + 32 * h;
            float s = 0.0f;
#pragma unroll
            for (int i = 0; i < 32; i++) s += S[o * 33 + i];
            const int b = b0 + wb + (o >> 3);
            const int j = j0 + wj + (o & 7);
            const float z = __ldcg(zrow + (size_t)b * HIDDEN + j);
            zrow[(size_t)b * HIDDEN + j] = fmaxf(tanhf(z + s), 0.0f);
        }
        __syncthreads();   // block done with scratch before next-iter Hsm fill
    }

    // h_last = outs[T-1] (own slice, own data — no barrier needed)
    const float* s = out + (size_t)(T_LEN - 1) * BH;
    float*       d = out + (size_t)T_LEN * BH;
    for (int i = tid; i < 512; i += NTHR) {
        int b = b0 + (i >> 5);
        int j = j0 + (i & 31);
        d[(size_t)b * HIDDEN + j] = s[(size_t)b * HIDDEN + j];
    }
}

extern "C" void kernel_launch(void* const* d_in, const int* in_sizes, int n_in,
                              void* d_out, int out_size)
{
    const int*   src = (const int*)  d_in[0];
    const float* emb = (const float*)d_in[1];
    const float* Wih = (const float*)d_in[2];
    const float* Whh = (const float*)d_in[3];
    const float* bih = (const float*)d_in[4];
    const float* bhh = (const float*)d_in[5];
    float* out = (float*)d_out;

    const int smem_bytes = (32 * 1024 + 8 * 64 * 33) * 4;  // 198656 B
    cudaFuncSetAttribute(rnn_persist,
                         cudaFuncAttributeMaxDynamicSharedMemorySize, smem_bytes);

    // 1) Z for all timesteps straight into the outs region of d_out
    dim3 g1(T_LEN * BATCH / 64, HIDDEN / 64);   // (512, 16)
    zgemm_kernel<<<g1, 256>>>(src, emb, Wih, bih, bhh, out);

    // 2) reset the grid barrier (fresh per launch / per graph replay)
    reset_bar<<<1, 1>>>();

    // 3) persistent recurrence: t=0 activation, 511 steps, h_last copy
    rnn_persist<<<NB, NTHR, smem_bytes>>>(Whh, out);
}